// round 9
// baseline (speedup 1.0000x reference)
#include <cuda_runtime.h>
#include <cuda_bf16.h>
#include <cstdint>
#include <math.h>

// Shapes: support [5,196,384], query [512,196,384], out [1,512,5]
#define NC 5
#define M_IMG 512
#define P 196
#define D 384

#define NEG_BIG (-1.0e30f)

#define SROWS 256            // padded support rows per class in g_sbf (zero-init)
#define BR 208               // resident query rows (26 n8 tiles)
#define NT8 26               // query n8 tiles
#define NCH 7                // support chunks per class (6x32 + 1x16 = 208 rows)
#define GCH (NC * NCH)       // 35 global chunks

#define B_KT_STRIDE (BR * 128)   // 26624 B per k-tile (query)
#define A_KT_STRIDE 4096         // 32 rows * 128B per k-tile (support chunk)
#define A_BUF_SIZE 24576         // 32 rows * 768B

// smem: [0..896) pmax | [1024..160768) B query | [160768..209920) A bufs x2
#define SM_B 1024
#define SM_A 160768
#define SM_TOTAL 209920

#define THREADS 128

// ---------------- staged data (allocation-free: __device__ globals) -----------
// query: raw bf16 (+64 zero pad rows: resident reads reach row 207 for m=511)
__device__ __align__(16) __nv_bfloat16 g_qbf[(M_IMG * P + 64) * D];
// support: L2-normalized bf16, padded to 256 rows/class (pad rows stay zero)
__device__ __align__(16) __nv_bfloat16 g_sbf[NC * SROWS * D];
// inverse L2 norm of each query row
__device__ float g_invq[M_IMG * P];

// ---------------- PTX helpers -------------------------------------------------
__device__ __forceinline__ uint32_t smem_u32(const void* p) {
    uint32_t a;
    asm("{ .reg .u64 t; cvta.to.shared.u64 t, %1; cvt.u32.u64 %0, t; }" : "=r"(a) : "l"(p));
    return a;
}
#define SW128(o) ((o) ^ (((o) >> 3) & 0x70))

__device__ __forceinline__ void cp_async16(uint32_t dst, const void* src) {
    asm volatile("cp.async.cg.shared.global [%0], [%1], 16;" :: "r"(dst), "l"(src));
}
__device__ __forceinline__ void cp_commit() { asm volatile("cp.async.commit_group;" ::: "memory"); }
template <int N>
__device__ __forceinline__ void cp_wait_n() {
    asm volatile("cp.async.wait_group %0;" :: "n"(N) : "memory");
}

#define LDSM_X4(r, addr) \
    asm volatile("ldmatrix.sync.aligned.m8n8.x4.shared.b16 {%0,%1,%2,%3}, [%4];" \
        : "=r"((r)[0]), "=r"((r)[1]), "=r"((r)[2]), "=r"((r)[3]) : "r"(addr))

#define LDSM_X2(r0, r1, addr) \
    asm volatile("ldmatrix.sync.aligned.m8n8.x2.shared.b16 {%0,%1}, [%2];" \
        : "=r"(r0), "=r"(r1) : "r"(addr))

#define MMA16816(c, a, b0, b1) \
    asm volatile("mma.sync.aligned.m16n8k16.row.col.f32.bf16.bf16.f32 " \
        "{%0,%1,%2,%3}, {%4,%5,%6,%7}, {%8,%9}, {%0,%1,%2,%3};" \
        : "+f"((c)[0]), "+f"((c)[1]), "+f"((c)[2]), "+f"((c)[3]) \
        : "r"((a)[0]), "r"((a)[1]), "r"((a)[2]), "r"((a)[3]), "r"(b0), "r"(b1))

// ---------------- Kernel 1: norms + bf16 staging ------------------------------
__global__ void stage_kernel(const float* __restrict__ support,
                             const float* __restrict__ query) {
    const int warp = (blockIdx.x * blockDim.x + threadIdx.x) >> 5;
    const int lane = threadIdx.x & 31;
    const int nq = M_IMG * P;
    const int nrows = nq + NC * P;
    if (warp >= nrows) return;

    const bool is_q = (warp < nq);
    const float* src = is_q ? (query + (size_t)warp * D)
                            : (support + (size_t)(warp - nq) * D);

    float4 v[3];
    float s = 0.0f;
    #pragma unroll
    for (int j = 0; j < 3; ++j) {
        v[j] = reinterpret_cast<const float4*>(src)[lane + 32 * j];
        s += v[j].x * v[j].x + v[j].y * v[j].y + v[j].z * v[j].z + v[j].w * v[j].w;
    }
    #pragma unroll
    for (int off = 16; off; off >>= 1) s += __shfl_xor_sync(0xffffffffu, s, off);
    const float inv = 1.0f / fmaxf(sqrtf(s), 1e-12f);

    if (is_q) {
        uint32_t* dst = reinterpret_cast<uint32_t*>(g_qbf + (size_t)warp * D);
        #pragma unroll
        for (int j = 0; j < 3; ++j) {
            const int k = lane + 32 * j;
            __nv_bfloat162 a = __floats2bfloat162_rn(v[j].x, v[j].y);
            __nv_bfloat162 b = __floats2bfloat162_rn(v[j].z, v[j].w);
            dst[2 * k]     = *reinterpret_cast<uint32_t*>(&a);
            dst[2 * k + 1] = *reinterpret_cast<uint32_t*>(&b);
        }
        if (lane == 0) g_invq[warp] = inv;
    } else {
        const int sr = warp - nq;
        const int c = sr / P, p = sr % P;
        uint32_t* dst = reinterpret_cast<uint32_t*>(g_sbf + ((size_t)c * SROWS + p) * D);
        #pragma unroll
        for (int j = 0; j < 3; ++j) {
            const int k = lane + 32 * j;
            __nv_bfloat162 a = __floats2bfloat162_rn(v[j].x * inv, v[j].y * inv);
            __nv_bfloat162 b = __floats2bfloat162_rn(v[j].z * inv, v[j].w * inv);
            dst[2 * k]     = *reinterpret_cast<uint32_t*>(&a);
            dst[2 * k + 1] = *reinterpret_cast<uint32_t*>(&b);
        }
    }
}

// ---------------- Kernel 2: query-resident fused HMMA + max + top6 ------------
// CTA per query image m. A operand = streamed support chunk (m16 rows),
// B operand = resident query (n8 cols). C[s,q]; max over s folds in-register.
__global__ __launch_bounds__(THREADS, 1)
void protonet_hmma_kernel(const float* __restrict__ scale_cls,
                          const float* __restrict__ bias,
                          float* __restrict__ out) {
    extern __shared__ char sm[];
    const uint32_t smb = smem_u32(sm);
    float* pmax = reinterpret_cast<float*>(sm);    // [224] per class, reused
    const int tid = threadIdx.x;
    const int w = tid >> 5;
    const int lane = tid & 31;
    const int m = blockIdx.x;

    const __nv_bfloat16* qbase = g_qbf + (size_t)m * P * D;
    const float* invq = g_invq + (size_t)m * P;

    // support chunk loader: global chunk g -> class g/7, chunk g%7; buf in {0,1}
    auto stage_s = [&](int g, int buf) {
        const int cls = g / NCH;
        const int ch = g - cls * NCH;
        const int rows = (ch == 6) ? 16 : 32;
        const __nv_bfloat16* sbase = g_sbf + ((size_t)cls * SROWS + ch * 32) * D;
        const uint32_t abase = smb + SM_A + buf * A_BUF_SIZE;
        const int n16 = rows * 8 * 6;
        for (int idx = tid; idx < n16; idx += THREADS) {
            const int kt  = idx / (rows * 8);
            const int rem = idx - kt * (rows * 8);
            const int row = rem >> 3;
            const int cb  = (rem & 7) << 4;
            const void* src = sbase + (size_t)row * D + kt * 64 + (cb >> 1);
            cp_async16(abase + kt * A_KT_STRIDE + SW128(row * 128 + cb), src);
        }
    };

    // prologue: resident query B (208 rows x 384), then support chunk 0
    for (int idx = tid; idx < BR * 8 * 6; idx += THREADS) {   // 9984 x 16B
        const int kt  = idx / (BR * 8);
        const int rem = idx - kt * (BR * 8);
        const int row = rem >> 3;
        const int cb  = (rem & 7) << 4;
        const void* src = qbase + (size_t)row * D + kt * 64 + (cb >> 1);
        cp_async16(smb + SM_B + kt * B_KT_STRIDE + SW128(row * 128 + cb), src);
    }
    cp_commit();
    stage_s(0, 0);
    cp_commit();

    // lane-derived LDSM addressing
    const int l7 = lane & 7;
    const int a_row = (((lane >> 3) & 1) << 3) + l7;   // support m16 fragment row
    const int a_kb  = ((lane >> 4) & 1) << 4;
    const int sel16 = ((lane >> 3) & 1) << 4;          // query x2: +16B for k 8..15

    // per-warp n8 tiles: t = w + 4i (i<7), valid while t < 26 (warp-uniform)
    float rmax[7][2];
    #pragma unroll
    for (int i = 0; i < 7; ++i) { rmax[i][0] = NEG_BIG; rmax[i][1] = NEG_BIG; }

    for (int g = 0; g < GCH; ++g) {
        if (g) __syncthreads();                 // compute g-1 done -> buf (g+1)&1 free
        if (g + 1 < GCH) {
            stage_s(g + 1, (g + 1) & 1);
            cp_commit();
            cp_wait_n<1>();                     // chunk g (+ B at g=0) arrived
        } else {
            cp_wait_n<0>();
        }
        __syncthreads();

        const uint32_t abase_ = smb + SM_A + (g & 1) * A_BUF_SIZE;
        const uint32_t bbase_ = smb + SM_B;
        const int ch = g % NCH;
        const int MT = (ch == 6) ? 1 : 2;       // tail chunk: 1 m16 (rows 192-207)

        float cacc[2][7][4];
        #pragma unroll
        for (int i = 0; i < 2; ++i)
            #pragma unroll
            for (int j = 0; j < 7; ++j)
                #pragma unroll
                for (int k = 0; k < 4; ++k) cacc[i][j][k] = 0.0f;

        for (int kt = 0; kt < 6; ++kt) {
            const uint32_t abase = abase_ + kt * A_KT_STRIDE;
            const uint32_t bbase = bbase_ + kt * B_KT_STRIDE;
            #pragma unroll
            for (int k16 = 0; k16 < 4; ++k16) {
                const int kb = k16 * 32;
                uint32_t a[2][4];
                LDSM_X4(a[0], abase + SW128(a_row * 128 + kb + a_kb));
                if (MT == 2)
                    LDSM_X4(a[1], abase + SW128((16 + a_row) * 128 + kb + a_kb));
                uint32_t b[7][2];
                #pragma unroll
                for (int i = 0; i < 7; ++i) {
                    const int t = w + 4 * i;
                    if (t < NT8)
                        LDSM_X2(b[i][0], b[i][1],
                                bbase + SW128((t * 8 + l7) * 128 + kb + sel16));
                }
                #pragma unroll
                for (int i = 0; i < 7; ++i) {
                    if (w + 4 * i < NT8) {
                        MMA16816(cacc[0][i], a[0], b[i][0], b[i][1]);
                        if (MT == 2)
                            MMA16816(cacc[1][i], a[1], b[i][0], b[i][1]);
                    }
                }
            }
        }

        // fold support-row max into per-lane running max
        if (MT == 2) {
            #pragma unroll
            for (int i = 0; i < 7; ++i) {
                if (w + 4 * i < NT8) {
                    rmax[i][0] = fmaxf(rmax[i][0],
                        fmaxf(fmaxf(cacc[0][i][0], cacc[0][i][2]),
                              fmaxf(cacc[1][i][0], cacc[1][i][2])));
                    rmax[i][1] = fmaxf(rmax[i][1],
                        fmaxf(fmaxf(cacc[0][i][1], cacc[0][i][3]),
                              fmaxf(cacc[1][i][1], cacc[1][i][3])));
                }
            }
        } else {
            // tail tile rows 192-207: c0/c1 row = 192+(lane>>2) valid iff lane<16;
            // c2/c3 rows 200+ never valid
            if (lane < 16) {
                #pragma unroll
                for (int i = 0; i < 7; ++i) {
                    if (w + 4 * i < NT8) {
                        rmax[i][0] = fmaxf(rmax[i][0], cacc[0][i][0]);
                        rmax[i][1] = fmaxf(rmax[i][1], cacc[0][i][1]);
                    }
                }
            }
        }

        if (ch == 6) {
            // ---- class end: reduce across fragment-row lanes, write pmax ----
            const int cls = g / NCH;
            #pragma unroll
            for (int i = 0; i < 7; ++i) {
                const int t = w + 4 * i;
                if (t < NT8) {
                    float v0 = rmax[i][0], v1 = rmax[i][1];
                    #pragma unroll
                    for (int off = 4; off <= 16; off <<= 1) {
                        v0 = fmaxf(v0, __shfl_xor_sync(0xffffffffu, v0, off));
                        v1 = fmaxf(v1, __shfl_xor_sync(0xffffffffu, v1, off));
                    }
                    if (lane < 4) {
                        const int q0 = t * 8 + 2 * lane;
                        if (q0 < P)     pmax[q0]     = v0 * invq[q0];
                        if (q0 + 1 < P) pmax[q0 + 1] = v1 * invq[q0 + 1];
                    }
                    rmax[i][0] = NEG_BIG; rmax[i][1] = NEG_BIG;
                }
            }
            __syncthreads();

            // warp 0: exact top-6 over pmax[0..195]
            if (w == 0) {
                float v[7];
                #pragma unroll
                for (int k = 0; k < 7; ++k) {
                    const int p = lane + 32 * k;
                    v[k] = (p < P) ? pmax[p] : NEG_BIG;
                }
                float total = 0.0f;
                for (int it = 0; it < 6; ++it) {
                    float bv = NEG_BIG; int bk = 0;
                    #pragma unroll
                    for (int k = 0; k < 7; ++k)
                        if (v[k] > bv) { bv = v[k]; bk = k; }
                    int bi = lane + 32 * bk;
                    #pragma unroll
                    for (int off = 16; off; off >>= 1) {
                        float ov = __shfl_xor_sync(0xffffffffu, bv, off);
                        int   oi = __shfl_xor_sync(0xffffffffu, bi, off);
                        if (ov > bv || (ov == bv && oi < bi)) { bv = ov; bi = oi; }
                    }
                    total += bv;
                    if ((bi & 31) == lane) v[bi >> 5] = NEG_BIG;
                }
                if (lane == 0) out[m * NC + cls] = scale_cls[0] * (total + bias[0]);
            }
        }
    }
}

// ---------------------------------------------------------------------------
extern "C" void kernel_launch(void* const* d_in, const int* in_sizes, int n_in,
                              void* d_out, int out_size) {
    const float* support   = (const float*)d_in[0];
    const float* query     = (const float*)d_in[1];
    const float* scale_cls = (const float*)d_in[2];
    const float* bias      = (const float*)d_in[3];
    float* out = (float*)d_out;

    // Stage 1: norms + bf16 conversion
    const int nrows = M_IMG * P + NC * P;
    const int blocks = (nrows * 32 + 255) / 256;
    stage_kernel<<<blocks, 256>>>(support, query);

    // Stage 2: fused HMMA GEMM + reductions (set attribute every call; capture-safe)
    cudaFuncSetAttribute(protonet_hmma_kernel,
                         cudaFuncAttributeMaxDynamicSharedMemorySize, SM_TOTAL);
    protonet_hmma_kernel<<<M_IMG, THREADS, SM_TOTAL>>>(scale_cls, bias, out);
}

// round 10
// speedup vs baseline: 1.1471x; 1.1471x over previous
#include <cuda_runtime.h>
#include <cuda_bf16.h>
#include <cstdint>
#include <math.h>

// Shapes: support [5,196,384], query [512,196,384], out [1,512,5]
#define NC 5
#define M_IMG 512
#define P 196
#define D 384

#define NEG_BIG (-1.0e30f)

#define SROWS 256            // padded support rows per class in g_sbf (zero-init)
#define BROWS 200            // resident support rows (25 n8 tiles, 2% pad)
#define NT8 25               // support n8 tiles
#define NCHUNK 7             // query chunks: 6x32 + 1x16 = 208 rows (13 m16)
#define QROWS 208

#define B_KT_STRIDE (BROWS * 128)  // 25600 B per k-tile (support)
#define A_KT_STRIDE 4096           // 32 rows * 128B per k-tile (query chunk)
#define A_BUF_SIZE 24576           // 32 rows * 768B

// smem: [0..3328) pmax4[4][208] | [4096..53248) A bufs x2 | [53248..206848) B
#define SM_A 4096
#define SM_B 53248
#define SM_TOTAL 206848

#define THREADS 128

// ---------------- staged data (allocation-free: __device__ globals) -----------
// query: raw bf16 (+64 zero pad rows: chunk reads reach row 207 for m=511)
__device__ __align__(16) __nv_bfloat16 g_qbf[(M_IMG * P + 64) * D];
// support: L2-normalized bf16, padded to 256 rows/class (pad rows stay zero)
__device__ __align__(16) __nv_bfloat16 g_sbf[NC * SROWS * D];
// inverse L2 norm of each query row
__device__ float g_invq[M_IMG * P];

// ---------------- PTX helpers -------------------------------------------------
__device__ __forceinline__ uint32_t smem_u32(const void* p) {
    uint32_t a;
    asm("{ .reg .u64 t; cvta.to.shared.u64 t, %1; cvt.u32.u64 %0, t; }" : "=r"(a) : "l"(p));
    return a;
}
#define SW128(o) ((o) ^ (((o) >> 3) & 0x70))

__device__ __forceinline__ void cp_async16(uint32_t dst, const void* src) {
    asm volatile("cp.async.cg.shared.global [%0], [%1], 16;" :: "r"(dst), "l"(src));
}
__device__ __forceinline__ void cp_commit() { asm volatile("cp.async.commit_group;" ::: "memory"); }
template <int N>
__device__ __forceinline__ void cp_wait_n() {
    asm volatile("cp.async.wait_group %0;" :: "n"(N) : "memory");
}

#define LDSM_X4(r, addr) \
    asm volatile("ldmatrix.sync.aligned.m8n8.x4.shared.b16 {%0,%1,%2,%3}, [%4];" \
        : "=r"((r)[0]), "=r"((r)[1]), "=r"((r)[2]), "=r"((r)[3]) : "r"(addr))

#define LDSM_X2(r0, r1, addr) \
    asm volatile("ldmatrix.sync.aligned.m8n8.x2.shared.b16 {%0,%1}, [%2];" \
        : "=r"(r0), "=r"(r1) : "r"(addr))

#define MMA16816(c, a, b0, b1) \
    asm volatile("mma.sync.aligned.m16n8k16.row.col.f32.bf16.bf16.f32 " \
        "{%0,%1,%2,%3}, {%4,%5,%6,%7}, {%8,%9}, {%0,%1,%2,%3};" \
        : "+f"((c)[0]), "+f"((c)[1]), "+f"((c)[2]), "+f"((c)[3]) \
        : "r"((a)[0]), "r"((a)[1]), "r"((a)[2]), "r"((a)[3]), "r"(b0), "r"(b1))

// ---------------- Kernel 1: norms + bf16 staging ------------------------------
__global__ void stage_kernel(const float* __restrict__ support,
                             const float* __restrict__ query) {
    const int warp = (blockIdx.x * blockDim.x + threadIdx.x) >> 5;
    const int lane = threadIdx.x & 31;
    const int nq = M_IMG * P;
    const int nrows = nq + NC * P;
    if (warp >= nrows) return;

    const bool is_q = (warp < nq);
    const float* src = is_q ? (query + (size_t)warp * D)
                            : (support + (size_t)(warp - nq) * D);

    float4 v[3];
    float s = 0.0f;
    #pragma unroll
    for (int j = 0; j < 3; ++j) {
        v[j] = reinterpret_cast<const float4*>(src)[lane + 32 * j];
        s += v[j].x * v[j].x + v[j].y * v[j].y + v[j].z * v[j].z + v[j].w * v[j].w;
    }
    #pragma unroll
    for (int off = 16; off; off >>= 1) s += __shfl_xor_sync(0xffffffffu, s, off);
    const float inv = 1.0f / fmaxf(sqrtf(s), 1e-12f);

    if (is_q) {
        uint32_t* dst = reinterpret_cast<uint32_t*>(g_qbf + (size_t)warp * D);
        #pragma unroll
        for (int j = 0; j < 3; ++j) {
            const int k = lane + 32 * j;
            __nv_bfloat162 a = __floats2bfloat162_rn(v[j].x, v[j].y);
            __nv_bfloat162 b = __floats2bfloat162_rn(v[j].z, v[j].w);
            dst[2 * k]     = *reinterpret_cast<uint32_t*>(&a);
            dst[2 * k + 1] = *reinterpret_cast<uint32_t*>(&b);
        }
        if (lane == 0) g_invq[warp] = inv;
    } else {
        const int sr = warp - nq;
        const int c = sr / P, p = sr % P;
        uint32_t* dst = reinterpret_cast<uint32_t*>(g_sbf + ((size_t)c * SROWS + p) * D);
        #pragma unroll
        for (int j = 0; j < 3; ++j) {
            const int k = lane + 32 * j;
            __nv_bfloat162 a = __floats2bfloat162_rn(v[j].x * inv, v[j].y * inv);
            __nv_bfloat162 b = __floats2bfloat162_rn(v[j].z * inv, v[j].w * inv);
            dst[2 * k]     = *reinterpret_cast<uint32_t*>(&a);
            dst[2 * k + 1] = *reinterpret_cast<uint32_t*>(&b);
        }
    }
}

// ---------------- shared per-k-tile GEMM body ---------------------------------
// A = query m16 tiles (MT of them), B = support n8 tiles t = w + 4i (t < 25).
__device__ __forceinline__ void gemm_kt_body(uint32_t abase, uint32_t bbase,
                                             int MT, int w, int lane,
                                             float (&cacc)[2][7][4]) {
    const int l7 = lane & 7;
    const int a_row = (((lane >> 3) & 1) << 3) + l7;
    const int a_kb  = ((lane >> 4) & 1) << 4;
    const int sel16 = ((lane >> 3) & 1) << 4;
    #pragma unroll
    for (int k16 = 0; k16 < 4; ++k16) {
        const int kb = k16 * 32;
        uint32_t a[2][4];
        LDSM_X4(a[0], abase + SW128(a_row * 128 + kb + a_kb));
        if (MT == 2)
            LDSM_X4(a[1], abase + SW128((16 + a_row) * 128 + kb + a_kb));
        uint32_t b[7][2];
        #pragma unroll
        for (int i = 0; i < 7; ++i) {
            const int t = w + 4 * i;
            if (t < NT8)
                LDSM_X2(b[i][0], b[i][1],
                        bbase + SW128((t * 8 + l7) * 128 + kb + sel16));
        }
        #pragma unroll
        for (int i = 0; i < 7; ++i) {
            if (w + 4 * i < NT8) {
                MMA16816(cacc[0][i], a[0], b[i][0], b[i][1]);
                if (MT == 2)
                    MMA16816(cacc[1][i], a[1], b[i][0], b[i][1]);
            }
        }
    }
}

// chunk-0 k-tile loop with incremental B waits (literal wait_group immediates).
// Pending groups after prologue commits: {A0, B0..B5, A1}. At step KT we need
// A0 + B0..BKT -> allowed pending = (5-KT) B tiles + A1 = 6-KT.
template <int KT>
__device__ __forceinline__ void chunk0_loop(uint32_t abase0, uint32_t bbase0,
                                            int w, int lane, float (&cacc)[2][7][4]) {
    if constexpr (KT < 6) {
        cp_wait_n<6 - KT>();
        __syncthreads();
        gemm_kt_body(abase0 + KT * A_KT_STRIDE, bbase0 + KT * B_KT_STRIDE,
                     2, w, lane, cacc);
        chunk0_loop<KT + 1>(abase0, bbase0, w, lane, cacc);
    }
}

// ---------------- Kernel 2: support-resident fused HMMA + max + top6 ----------
__global__ __launch_bounds__(THREADS, 1)
void protonet_hmma_kernel(const float* __restrict__ scale_cls,
                          const float* __restrict__ bias,
                          float* __restrict__ out) {
    extern __shared__ char sm[];
    const uint32_t smb = smem_u32(sm);
    float* pmax4 = reinterpret_cast<float*>(sm);   // [4][208] per-warp partials
    const int tid = threadIdx.x;
    const int w = tid >> 5;
    const int lane = tid & 31;
    const int c = blockIdx.x;    // class fast -> query chunk L2 reuse
    const int m = blockIdx.y;

    const __nv_bfloat16* qbase = g_qbf + (size_t)m * P * D;
    const __nv_bfloat16* sbase = g_sbf + (size_t)c * SROWS * D;

    // query chunk loader: chunk ch (32 rows, tail ch=6: 16 rows) -> buf
    auto stage_a = [&](int ch, int buf) {
        const int rows = (ch == 6) ? 16 : 32;
        const uint32_t abase = smb + SM_A + buf * A_BUF_SIZE;
        const int n16 = rows * 8 * 6;
        for (int idx = tid; idx < n16; idx += THREADS) {
            const int kt  = idx / (rows * 8);
            const int rem = idx - kt * (rows * 8);
            const int row = rem >> 3;
            const int cb  = (rem & 7) << 4;
            const void* src = qbase + (size_t)(ch * 32 + row) * D + kt * 64 + (cb >> 1);
            cp_async16(abase + kt * A_KT_STRIDE + SW128(row * 128 + cb), src);
        }
        cp_commit();
    };

    // prologue: A chunk 0 (group), B as 6 per-k-tile groups, A chunk 1 (group)
    stage_a(0, 0);
    #pragma unroll
    for (int kt = 0; kt < 6; ++kt) {
        for (int idx = tid; idx < BROWS * 8; idx += THREADS) {   // 1600 x 16B
            const int row = idx >> 3;
            const int cb  = (idx & 7) << 4;
            const void* src = sbase + (size_t)row * D + kt * 64 + (cb >> 1);
            cp_async16(smb + SM_B + kt * B_KT_STRIDE + SW128(row * 128 + cb), src);
        }
        cp_commit();
    }
    stage_a(1, 1);

    // ---- chunk 0 (rows 0..31), B streaming under compute ----
    float cacc[2][7][4];
    #pragma unroll
    for (int i = 0; i < 2; ++i)
        #pragma unroll
        for (int j = 0; j < 7; ++j)
            #pragma unroll
            for (int k = 0; k < 4; ++k) cacc[i][j][k] = 0.0f;

    chunk0_loop<0>(smb + SM_A, smb + SM_B, w, lane, cacc);

    // fold + write partials for a finished chunk
    auto finish_chunk = [&](int ch, int MT, float (&cc)[2][7][4]) {
        float rmax[2][2];
        rmax[0][0] = rmax[0][1] = rmax[1][0] = rmax[1][1] = NEG_BIG;
        #pragma unroll
        for (int i = 0; i < 7; ++i) {
            const int t = w + 4 * i;
            if (t < NT8) {
                const int col0 = t * 8 + ((lane & 3) << 1);
                if (col0 < P) {   // support cols masked (pairs align at 196)
                    rmax[0][0] = fmaxf(rmax[0][0], fmaxf(cc[0][i][0], cc[0][i][1]));
                    rmax[0][1] = fmaxf(rmax[0][1], fmaxf(cc[0][i][2], cc[0][i][3]));
                    if (MT == 2) {
                        rmax[1][0] = fmaxf(rmax[1][0], fmaxf(cc[1][i][0], cc[1][i][1]));
                        rmax[1][1] = fmaxf(rmax[1][1], fmaxf(cc[1][i][2], cc[1][i][3]));
                    }
                }
            }
        }
        #pragma unroll
        for (int mt = 0; mt < 2; ++mt) {
            if (mt < MT) {
                float v0 = rmax[mt][0], v1 = rmax[mt][1];
                #pragma unroll
                for (int off = 1; off <= 2; off <<= 1) {
                    v0 = fmaxf(v0, __shfl_xor_sync(0xffffffffu, v0, off));
                    v1 = fmaxf(v1, __shfl_xor_sync(0xffffffffu, v1, off));
                }
                if ((lane & 3) == 0) {
                    const int r = ch * 32 + mt * 16 + (lane >> 2);
                    pmax4[w * QROWS + r]     = v0;
                    pmax4[w * QROWS + r + 8] = v1;
                }
            }
        }
    };
    finish_chunk(0, 2, cacc);

    // ---- chunks 1..6 ----
    for (int ch = 1; ch < NCHUNK; ++ch) {
        __syncthreads();               // compute ch-1 done -> buf (ch+1)&1 free
        if (ch + 1 < NCHUNK) { stage_a(ch + 1, (ch + 1) & 1); cp_wait_n<1>(); }
        else                 { cp_wait_n<0>(); }
        __syncthreads();

        const uint32_t abase_ = smb + SM_A + (ch & 1) * A_BUF_SIZE;
        const int MT = (ch == 6) ? 1 : 2;

        #pragma unroll
        for (int i = 0; i < 2; ++i)
            #pragma unroll
            for (int j = 0; j < 7; ++j)
                #pragma unroll
                for (int k = 0; k < 4; ++k) cacc[i][j][k] = 0.0f;

        for (int kt = 0; kt < 6; ++kt)   // barrier-free: B fully resident now
            gemm_kt_body(abase_ + kt * A_KT_STRIDE, smb + SM_B + kt * B_KT_STRIDE,
                         MT, w, lane, cacc);

        finish_chunk(ch, MT, cacc);
    }
    __syncthreads();

    // combine 4 warp-partials per query row, apply invq
    const float* invq = g_invq + (size_t)m * P;
    for (int r = tid; r < P; r += THREADS) {
        float v = fmaxf(fmaxf(pmax4[r], pmax4[QROWS + r]),
                        fmaxf(pmax4[2 * QROWS + r], pmax4[3 * QROWS + r]));
        pmax4[r] = v * invq[r];
    }
    __syncthreads();

    // warp 0: exact top-6 over pmax4[0..195]
    if (w == 0) {
        float v[7];
        #pragma unroll
        for (int k = 0; k < 7; ++k) {
            const int p = lane + 32 * k;
            v[k] = (p < P) ? pmax4[p] : NEG_BIG;
        }
        float total = 0.0f;
        for (int it = 0; it < 6; ++it) {
            float bv = NEG_BIG; int bk = 0;
            #pragma unroll
            for (int k = 0; k < 7; ++k)
                if (v[k] > bv) { bv = v[k]; bk = k; }
            int bi = lane + 32 * bk;
            #pragma unroll
            for (int off = 16; off; off >>= 1) {
                float ov = __shfl_xor_sync(0xffffffffu, bv, off);
                int   oi = __shfl_xor_sync(0xffffffffu, bi, off);
                if (ov > bv || (ov == bv && oi < bi)) { bv = ov; bi = oi; }
            }
            total += bv;
            if ((bi & 31) == lane) v[bi >> 5] = NEG_BIG;
        }
        if (lane == 0) out[m * NC + c] = scale_cls[0] * (total + bias[0]);
    }
}

// ---------------------------------------------------------------------------
extern "C" void kernel_launch(void* const* d_in, const int* in_sizes, int n_in,
                              void* d_out, int out_size) {
    const float* support   = (const float*)d_in[0];
    const float* query     = (const float*)d_in[1];
    const float* scale_cls = (const float*)d_in[2];
    const float* bias      = (const float*)d_in[3];
    float* out = (float*)d_out;

    // Stage 1: norms + bf16 conversion
    const int nrows = M_IMG * P + NC * P;
    const int blocks = (nrows * 32 + 255) / 256;
    stage_kernel<<<blocks, 256>>>(support, query);

    // Stage 2: fused HMMA GEMM + reductions (set attribute every call; capture-safe)
    cudaFuncSetAttribute(protonet_hmma_kernel,
                         cudaFuncAttributeMaxDynamicSharedMemorySize, SM_TOTAL);
    dim3 grid(NC, M_IMG);
    protonet_hmma_kernel<<<grid, THREADS, SM_TOTAL>>>(scale_cls, bias, out);
}

// round 11
// speedup vs baseline: 1.3484x; 1.1755x over previous
#include <cuda_runtime.h>
#include <cuda_bf16.h>
#include <cstdint>
#include <math.h>

// Shapes: support [5,196,384], query [512,196,384], out [1,512,5]
#define NC 5
#define M_IMG 512
#define P 196
#define D 384

#define NEG_BIG (-1.0e30f)

#define SROWS 256            // padded support rows per class in g_sbf (zero-init)
#define BROWS 200            // resident support rows (25 n8 tiles, 2% pad)
#define NT8 25               // support n8 tiles
#define NCHUNK 7             // query chunks: 6x32 + 1x16 = 208 rows (13 m16)
#define QROWS 208

#define B_KT_STRIDE (BROWS * 128)  // 25600 B per k-tile (support)
#define A_KT_STRIDE 4096           // 32 rows * 128B per k-tile (query chunk)
#define A_BUF_SIZE 24576           // 32 rows * 768B

// smem: [0..3328) pmax4[4][208] | [4096..53248) A bufs x2 | [53248..206848) B
#define SM_A 4096
#define SM_B 53248
#define SM_TOTAL 206848

#define THREADS 128

// ---------------- staged data (allocation-free: __device__ globals) -----------
// query: raw bf16 (+64 zero pad rows: chunk reads reach row 207 for m=511)
__device__ __align__(16) __nv_bfloat16 g_qbf[(M_IMG * P + 64) * D];
// support: L2-normalized bf16, padded to 256 rows/class (pad rows stay zero)
__device__ __align__(16) __nv_bfloat16 g_sbf[NC * SROWS * D];
// inverse L2 norm of each query row
__device__ float g_invq[M_IMG * P];

// ---------------- PTX helpers -------------------------------------------------
__device__ __forceinline__ uint32_t smem_u32(const void* p) {
    uint32_t a;
    asm("{ .reg .u64 t; cvta.to.shared.u64 t, %1; cvt.u32.u64 %0, t; }" : "=r"(a) : "l"(p));
    return a;
}
#define SW128(o) ((o) ^ (((o) >> 3) & 0x70))

__device__ __forceinline__ void cp_async16(uint32_t dst, const void* src) {
    asm volatile("cp.async.cg.shared.global [%0], [%1], 16;" :: "r"(dst), "l"(src));
}
__device__ __forceinline__ void cp_commit() { asm volatile("cp.async.commit_group;" ::: "memory"); }
template <int N>
__device__ __forceinline__ void cp_wait_n() {
    asm volatile("cp.async.wait_group %0;" :: "n"(N) : "memory");
}

#define LDSM_X4(r, addr) \
    asm volatile("ldmatrix.sync.aligned.m8n8.x4.shared.b16 {%0,%1,%2,%3}, [%4];" \
        : "=r"((r)[0]), "=r"((r)[1]), "=r"((r)[2]), "=r"((r)[3]) : "r"(addr))

#define LDSM_X2(r0, r1, addr) \
    asm volatile("ldmatrix.sync.aligned.m8n8.x2.shared.b16 {%0,%1}, [%2];" \
        : "=r"(r0), "=r"(r1) : "r"(addr))

#define MMA16816(c, a, b0, b1) \
    asm volatile("mma.sync.aligned.m16n8k16.row.col.f32.bf16.bf16.f32 " \
        "{%0,%1,%2,%3}, {%4,%5,%6,%7}, {%8,%9}, {%0,%1,%2,%3};" \
        : "+f"((c)[0]), "+f"((c)[1]), "+f"((c)[2]), "+f"((c)[3]) \
        : "r"((a)[0]), "r"((a)[1]), "r"((a)[2]), "r"((a)[3]), "r"(b0), "r"(b1))

// ---------------- Kernel 1: norms + bf16 staging ------------------------------
__global__ void stage_kernel(const float* __restrict__ support,
                             const float* __restrict__ query) {
    const int warp = (blockIdx.x * blockDim.x + threadIdx.x) >> 5;
    const int lane = threadIdx.x & 31;
    const int nq = M_IMG * P;
    const int nrows = nq + NC * P;
    if (warp >= nrows) return;

    const bool is_q = (warp < nq);
    const float* src = is_q ? (query + (size_t)warp * D)
                            : (support + (size_t)(warp - nq) * D);

    float4 v[3];
    float s = 0.0f;
    #pragma unroll
    for (int j = 0; j < 3; ++j) {
        v[j] = reinterpret_cast<const float4*>(src)[lane + 32 * j];
        s += v[j].x * v[j].x + v[j].y * v[j].y + v[j].z * v[j].z + v[j].w * v[j].w;
    }
    #pragma unroll
    for (int off = 16; off; off >>= 1) s += __shfl_xor_sync(0xffffffffu, s, off);
    const float inv = 1.0f / fmaxf(sqrtf(s), 1e-12f);

    if (is_q) {
        uint32_t* dst = reinterpret_cast<uint32_t*>(g_qbf + (size_t)warp * D);
        #pragma unroll
        for (int j = 0; j < 3; ++j) {
            const int k = lane + 32 * j;
            __nv_bfloat162 a = __floats2bfloat162_rn(v[j].x, v[j].y);
            __nv_bfloat162 b = __floats2bfloat162_rn(v[j].z, v[j].w);
            dst[2 * k]     = *reinterpret_cast<uint32_t*>(&a);
            dst[2 * k + 1] = *reinterpret_cast<uint32_t*>(&b);
        }
        if (lane == 0) g_invq[warp] = inv;
    } else {
        const int sr = warp - nq;
        const int c = sr / P, p = sr % P;
        uint32_t* dst = reinterpret_cast<uint32_t*>(g_sbf + ((size_t)c * SROWS + p) * D);
        #pragma unroll
        for (int j = 0; j < 3; ++j) {
            const int k = lane + 32 * j;
            __nv_bfloat162 a = __floats2bfloat162_rn(v[j].x * inv, v[j].y * inv);
            __nv_bfloat162 b = __floats2bfloat162_rn(v[j].z * inv, v[j].w * inv);
            dst[2 * k]     = *reinterpret_cast<uint32_t*>(&a);
            dst[2 * k + 1] = *reinterpret_cast<uint32_t*>(&b);
        }
    }
}

// ---------------- fully specialized per-k-tile GEMM body ----------------------
// W = warp id (compile-time), MT = query m16 tiles (2 or 1 for tail chunk).
// B tiles t = W + 4i while t < 25 -> NTW = 7 (W=0) or 6 (W>0). Branch-free.
template <int W, int MT>
__device__ __forceinline__ void gemm_kt_body(uint32_t abase, uint32_t bbase,
                                             int lane, float (&cacc)[2][7][4]) {
    constexpr int NTW = (W == 0) ? 7 : 6;
    const int l7 = lane & 7;
    const int a_row = (((lane >> 3) & 1) << 3) + l7;
    const int a_kb  = ((lane >> 4) & 1) << 4;
    const int sel16 = ((lane >> 3) & 1) << 4;
    #pragma unroll
    for (int k16 = 0; k16 < 4; ++k16) {
        const int kb = k16 * 32;
        uint32_t a[2][4];
        LDSM_X4(a[0], abase + SW128(a_row * 128 + kb + a_kb));
        if constexpr (MT == 2)
            LDSM_X4(a[1], abase + SW128((16 + a_row) * 128 + kb + a_kb));
        uint32_t b[NTW][2];
        #pragma unroll
        for (int i = 0; i < NTW; ++i) {
            constexpr int base_t = W;
            const int t = base_t + 4 * i;   // compile-time after unroll
            LDSM_X2(b[i][0], b[i][1],
                    bbase + SW128((t * 8 + l7) * 128 + kb + sel16));
        }
        #pragma unroll
        for (int i = 0; i < NTW; ++i) {
            MMA16816(cacc[0][i], a[0], b[i][0], b[i][1]);
            if constexpr (MT == 2)
                MMA16816(cacc[1][i], a[1], b[i][0], b[i][1]);
        }
    }
}

// warp-uniform dispatch (branch taken once per call; body is branch-free)
template <int MT>
__device__ __forceinline__ void gemm_kt(uint32_t abase, uint32_t bbase,
                                        int w, int lane, float (&cacc)[2][7][4]) {
    switch (w) {
        case 0:  gemm_kt_body<0, MT>(abase, bbase, lane, cacc); break;
        case 1:  gemm_kt_body<1, MT>(abase, bbase, lane, cacc); break;
        case 2:  gemm_kt_body<2, MT>(abase, bbase, lane, cacc); break;
        default: gemm_kt_body<3, MT>(abase, bbase, lane, cacc); break;
    }
}

// chunk-0 k-tile loop with incremental B waits (literal wait_group immediates).
// Pending after prologue commits: {A0, B0..B5, A1}. At step KT we need
// A0 + B0..BKT -> allowed pending = (5-KT) B tiles + A1 = 6-KT.
template <int KT>
__device__ __forceinline__ void chunk0_loop(uint32_t abase0, uint32_t bbase0,
                                            int w, int lane, float (&cacc)[2][7][4]) {
    if constexpr (KT < 6) {
        cp_wait_n<6 - KT>();
        __syncthreads();
        gemm_kt<2>(abase0 + KT * A_KT_STRIDE, bbase0 + KT * B_KT_STRIDE,
                   w, lane, cacc);
        chunk0_loop<KT + 1>(abase0, bbase0, w, lane, cacc);
    }
}

// ---------------- Kernel 2: support-resident fused HMMA + max + top6 ----------
__global__ __launch_bounds__(THREADS, 1)
void protonet_hmma_kernel(const float* __restrict__ scale_cls,
                          const float* __restrict__ bias,
                          float* __restrict__ out) {
    extern __shared__ char sm[];
    const uint32_t smb = smem_u32(sm);
    float* pmax4 = reinterpret_cast<float*>(sm);   // [4][208] per-warp partials
    const int tid = threadIdx.x;
    const int w = tid >> 5;
    const int lane = tid & 31;
    const int c = blockIdx.x;    // class fast -> query chunk L2 reuse
    const int m = blockIdx.y;

    const __nv_bfloat16* qbase = g_qbf + (size_t)m * P * D;
    const __nv_bfloat16* sbase = g_sbf + (size_t)c * SROWS * D;

    // query chunk loader: chunk ch (32 rows; tail ch=6 loads 16 rows) -> buf
    auto stage_a = [&](int ch, int buf) {
        const int rows = (ch == 6) ? 16 : 32;
        const uint32_t abase = smb + SM_A + buf * A_BUF_SIZE;
        const int n16 = rows * 8 * 6;
        for (int idx = tid; idx < n16; idx += THREADS) {
            const int kt  = idx / (rows * 8);
            const int rem = idx - kt * (rows * 8);
            const int row = rem >> 3;
            const int cb  = (rem & 7) << 4;
            const void* src = qbase + (size_t)(ch * 32 + row) * D + kt * 64 + (cb >> 1);
            cp_async16(abase + kt * A_KT_STRIDE + SW128(row * 128 + cb), src);
        }
        cp_commit();
    };

    // prologue: A chunk 0 (1 group), B as 6 per-k-tile groups, A chunk 1 (1 group)
    stage_a(0, 0);
    #pragma unroll
    for (int kt = 0; kt < 6; ++kt) {
        for (int idx = tid; idx < BROWS * 8; idx += THREADS) {   // 1600 x 16B
            const int row = idx >> 3;
            const int cb  = (idx & 7) << 4;
            const void* src = sbase + (size_t)row * D + kt * 64 + (cb >> 1);
            cp_async16(smb + SM_B + kt * B_KT_STRIDE + SW128(row * 128 + cb), src);
        }
        cp_commit();
    }
    stage_a(1, 1);

    auto reset_acc = [](float (&cc)[2][7][4]) {
        #pragma unroll
        for (int i = 0; i < 2; ++i)
            #pragma unroll
            for (int j = 0; j < 7; ++j)
                #pragma unroll
                for (int k = 0; k < 4; ++k) cc[i][j][k] = 0.0f;
    };

    // fold + write per-warp partials for a finished chunk (outside hot loop)
    auto finish_chunk = [&](int ch, int MT, float (&cc)[2][7][4]) {
        float rmax[2][2];
        rmax[0][0] = rmax[0][1] = rmax[1][0] = rmax[1][1] = NEG_BIG;
        #pragma unroll
        for (int i = 0; i < 7; ++i) {
            const int t = w + 4 * i;
            if (t < NT8) {
                const int col0 = t * 8 + ((lane & 3) << 1);
                if (col0 < P) {   // support col pair valid (196 is even)
                    rmax[0][0] = fmaxf(rmax[0][0], fmaxf(cc[0][i][0], cc[0][i][1]));
                    rmax[0][1] = fmaxf(rmax[0][1], fmaxf(cc[0][i][2], cc[0][i][3]));
                    if (MT == 2) {
                        rmax[1][0] = fmaxf(rmax[1][0], fmaxf(cc[1][i][0], cc[1][i][1]));
                        rmax[1][1] = fmaxf(rmax[1][1], fmaxf(cc[1][i][2], cc[1][i][3]));
                    }
                }
            }
        }
        #pragma unroll
        for (int mt = 0; mt < 2; ++mt) {
            if (mt < MT) {
                float v0 = rmax[mt][0], v1 = rmax[mt][1];
                #pragma unroll
                for (int off = 1; off <= 2; off <<= 1) {
                    v0 = fmaxf(v0, __shfl_xor_sync(0xffffffffu, v0, off));
                    v1 = fmaxf(v1, __shfl_xor_sync(0xffffffffu, v1, off));
                }
                if ((lane & 3) == 0) {
                    const int r = ch * 32 + mt * 16 + (lane >> 2);
                    pmax4[w * QROWS + r]     = v0;
                    pmax4[w * QROWS + r + 8] = v1;
                }
            }
        }
    };

    float cacc[2][7][4];

    // ---- chunk 0: B streams under compute via incremental waits ----
    reset_acc(cacc);
    chunk0_loop<0>(smb + SM_A, smb + SM_B, w, lane, cacc);
    finish_chunk(0, 2, cacc);

    // ---- chunks 1..5 (MT=2), double-buffered ----
    for (int ch = 1; ch < 6; ++ch) {
        __syncthreads();               // compute ch-1 done -> buf (ch+1)&1 free
        stage_a(ch + 1, (ch + 1) & 1); // stages chunks 2..6
        cp_wait_n<1>();                // chunk ch arrived
        __syncthreads();

        const uint32_t abase_ = smb + SM_A + (ch & 1) * A_BUF_SIZE;
        reset_acc(cacc);
        for (int kt = 0; kt < 6; ++kt)
            gemm_kt<2>(abase_ + kt * A_KT_STRIDE, smb + SM_B + kt * B_KT_STRIDE,
                       w, lane, cacc);
        finish_chunk(ch, 2, cacc);
    }

    // ---- tail chunk 6 (MT=1, rows 192..207) ----
    {
        __syncthreads();
        cp_wait_n<0>();
        __syncthreads();
        const uint32_t abase_ = smb + SM_A + (6 & 1) * A_BUF_SIZE;
        reset_acc(cacc);
        for (int kt = 0; kt < 6; ++kt)
            gemm_kt<1>(abase_ + kt * A_KT_STRIDE, smb + SM_B + kt * B_KT_STRIDE,
                       w, lane, cacc);
        finish_chunk(6, 1, cacc);
    }
    __syncthreads();

    // combine 4 warp-partials per query row, apply invq
    const float* invq = g_invq + (size_t)m * P;
    for (int r = tid; r < P; r += THREADS) {
        float v = fmaxf(fmaxf(pmax4[r], pmax4[QROWS + r]),
                        fmaxf(pmax4[2 * QROWS + r], pmax4[3 * QROWS + r]));
        pmax4[r] = v * invq[r];
    }
    __syncthreads();

    // warp 0: exact top-6 over pmax4[0..195]
    if (w == 0) {
        float v[7];
        #pragma unroll
        for (int k = 0; k < 7; ++k) {
            const int p = lane + 32 * k;
            v[k] = (p < P) ? pmax4[p] : NEG_BIG;
        }
        float total = 0.0f;
        for (int it = 0; it < 6; ++it) {
            float bv = NEG_BIG; int bk = 0;
            #pragma unroll
            for (int k = 0; k < 7; ++k)
                if (v[k] > bv) { bv = v[k]; bk = k; }
            int bi = lane + 32 * bk;
            #pragma unroll
            for (int off = 16; off; off >>= 1) {
                float ov = __shfl_xor_sync(0xffffffffu, bv, off);
                int   oi = __shfl_xor_sync(0xffffffffu, bi, off);
                if (ov > bv || (ov == bv && oi < bi)) { bv = ov; bi = oi; }
            }
            total += bv;
            if ((bi & 31) == lane) v[bi >> 5] = NEG_BIG;
        }
        if (lane == 0) out[m * NC + c] = scale_cls[0] * (total + bias[0]);
    }
}

// ---------------------------------------------------------------------------
extern "C" void kernel_launch(void* const* d_in, const int* in_sizes, int n_in,
                              void* d_out, int out_size) {
    const float* support   = (const float*)d_in[0];
    const float* query     = (const float*)d_in[1];
    const float* scale_cls = (const float*)d_in[2];
    const float* bias      = (const float*)d_in[3];
    float* out = (float*)d_out;

    // Stage 1: norms + bf16 conversion
    const int nrows = M_IMG * P + NC * P;
    const int blocks = (nrows * 32 + 255) / 256;
    stage_kernel<<<blocks, 256>>>(support, query);

    // Stage 2: fused HMMA GEMM + reductions (set attribute every call; capture-safe)
    cudaFuncSetAttribute(protonet_hmma_kernel,
                         cudaFuncAttributeMaxDynamicSharedMemorySize, SM_TOTAL);
    dim3 grid(NC, M_IMG);
    protonet_hmma_kernel<<<grid, THREADS, SM_TOTAL>>>(scale_cls, bias, out);
}

// round 12
// speedup vs baseline: 1.6051x; 1.1904x over previous
#include <cuda_runtime.h>
#include <cuda_bf16.h>
#include <cstdint>
#include <math.h>

// Shapes: support [5,196,384], query [512,196,384], out [1,512,5]
#define NC 5
#define M_IMG 512
#define P 196
#define D 384

#define NEG_BIG (-1.0e30f)

#define SROWS 256           // padded support rows per class in g_sbf (zero-init)
#define BROWS 224           // resident support rows (28 n8 tiles, uniform 7/warp)
#define NT8 28              // support n8 tiles
#define A_CH_ROWS 32        // query chunk rows (2 m16 tiles)
#define NCHUNK 7            // 7 * 32 = 224 query rows (>=196, pad garbage ignored)

#define B_KT_STRIDE (BROWS * 128)     // 28672 B per k-tile
#define A_KT_STRIDE (A_CH_ROWS * 128) // 4096  B per k-tile
#define A_BUF_SIZE (A_CH_ROWS * 768)  // 24576 B per chunk buffer

// smem layout: [0..3584) pmax4[4][224] | [4096..53248) A bufs x2 | [53248..225280) B
#define SM_PM 0
#define SM_A 4096
#define SM_B 53248
#define SM_TOTAL 225280

#define THREADS 128

// ---------------- staged data (allocation-free: __device__ globals) -----------
// query: raw bf16 (+64 zero pad rows: chunk reads reach row 223 for m=511)
__device__ __align__(16) __nv_bfloat16 g_qbf[(M_IMG * P + 64) * D];
// support: L2-normalized bf16, padded to 256 rows/class (pad rows stay zero)
__device__ __align__(16) __nv_bfloat16 g_sbf[NC * SROWS * D];
// inverse L2 norm of each query row
__device__ float g_invq[M_IMG * P];

// ---------------- PTX helpers -------------------------------------------------
__device__ __forceinline__ uint32_t smem_u32(const void* p) {
    uint32_t a;
    asm("{ .reg .u64 t; cvta.to.shared.u64 t, %1; cvt.u32.u64 %0, t; }" : "=r"(a) : "l"(p));
    return a;
}
#define SW128(o) ((o) ^ (((o) >> 3) & 0x70))

__device__ __forceinline__ void cp_async16(uint32_t dst, const void* src) {
    asm volatile("cp.async.cg.shared.global [%0], [%1], 16;" :: "r"(dst), "l"(src));
}
__device__ __forceinline__ void cp_commit() { asm volatile("cp.async.commit_group;" ::: "memory"); }
template <int N>
__device__ __forceinline__ void cp_wait_n() {
    asm volatile("cp.async.wait_group %0;" :: "n"(N) : "memory");
}

#define LDSM_X4(r, addr) \
    asm volatile("ldmatrix.sync.aligned.m8n8.x4.shared.b16 {%0,%1,%2,%3}, [%4];" \
        : "=r"((r)[0]), "=r"((r)[1]), "=r"((r)[2]), "=r"((r)[3]) : "r"(addr))

#define LDSM_X2(r0, r1, addr) \
    asm volatile("ldmatrix.sync.aligned.m8n8.x2.shared.b16 {%0,%1}, [%2];" \
        : "=r"(r0), "=r"(r1) : "r"(addr))

#define MMA16816(c, a, b0, b1) \
    asm volatile("mma.sync.aligned.m16n8k16.row.col.f32.bf16.bf16.f32 " \
        "{%0,%1,%2,%3}, {%4,%5,%6,%7}, {%8,%9}, {%0,%1,%2,%3};" \
        : "+f"((c)[0]), "+f"((c)[1]), "+f"((c)[2]), "+f"((c)[3]) \
        : "r"((a)[0]), "r"((a)[1]), "r"((a)[2]), "r"((a)[3]), "r"(b0), "r"(b1))

// ---------------- Kernel 1: norms + bf16 staging ------------------------------
__global__ void stage_kernel(const float* __restrict__ support,
                             const float* __restrict__ query) {
    const int warp = (blockIdx.x * blockDim.x + threadIdx.x) >> 5;
    const int lane = threadIdx.x & 31;
    const int nq = M_IMG * P;
    const int nrows = nq + NC * P;
    if (warp >= nrows) return;

    const bool is_q = (warp < nq);
    const float* src = is_q ? (query + (size_t)warp * D)
                            : (support + (size_t)(warp - nq) * D);

    float4 v[3];
    float s = 0.0f;
    #pragma unroll
    for (int j = 0; j < 3; ++j) {
        v[j] = reinterpret_cast<const float4*>(src)[lane + 32 * j];
        s += v[j].x * v[j].x + v[j].y * v[j].y + v[j].z * v[j].z + v[j].w * v[j].w;
    }
    #pragma unroll
    for (int off = 16; off; off >>= 1) s += __shfl_xor_sync(0xffffffffu, s, off);
    const float inv = 1.0f / fmaxf(sqrtf(s), 1e-12f);

    if (is_q) {
        uint32_t* dst = reinterpret_cast<uint32_t*>(g_qbf + (size_t)warp * D);
        #pragma unroll
        for (int j = 0; j < 3; ++j) {
            const int k = lane + 32 * j;
            __nv_bfloat162 a = __floats2bfloat162_rn(v[j].x, v[j].y);
            __nv_bfloat162 b = __floats2bfloat162_rn(v[j].z, v[j].w);
            dst[2 * k]     = *reinterpret_cast<uint32_t*>(&a);
            dst[2 * k + 1] = *reinterpret_cast<uint32_t*>(&b);
        }
        if (lane == 0) g_invq[warp] = inv;
    } else {
        const int sr = warp - nq;
        const int c = sr / P, p = sr % P;
        uint32_t* dst = reinterpret_cast<uint32_t*>(g_sbf + ((size_t)c * SROWS + p) * D);
        #pragma unroll
        for (int j = 0; j < 3; ++j) {
            const int k = lane + 32 * j;
            __nv_bfloat162 a = __floats2bfloat162_rn(v[j].x * inv, v[j].y * inv);
            __nv_bfloat162 b = __floats2bfloat162_rn(v[j].z * inv, v[j].w * inv);
            dst[2 * k]     = *reinterpret_cast<uint32_t*>(&a);
            dst[2 * k + 1] = *reinterpret_cast<uint32_t*>(&b);
        }
    }
}

// ---------------- per-k-tile GEMM body (R7 form: uniform, branch-free) --------
// A = query chunk (2 m16 tiles), B = support n8 tiles t = w + 4i, i<7 (all 28 valid).
__device__ __forceinline__ void gemm_kt_r7(uint32_t abase, uint32_t bbase,
                                           int w, int lane, float (&cacc)[2][7][4]) {
    const int l7 = lane & 7;
    const int a_row = (((lane >> 3) & 1) << 3) + l7;
    const int a_kb  = ((lane >> 4) & 1) << 4;
    const int sel16 = ((lane >> 3) & 1) << 4;
    #pragma unroll
    for (int k16 = 0; k16 < 4; ++k16) {
        const int kb = k16 * 32;
        uint32_t a[2][4];
        LDSM_X4(a[0], abase + SW128(a_row * 128 + kb + a_kb));
        LDSM_X4(a[1], abase + SW128((16 + a_row) * 128 + kb + a_kb));
        uint32_t b[7][2];
        #pragma unroll
        for (int i = 0; i < 7; ++i) {
            const int t = w + 4 * i;
            LDSM_X2(b[i][0], b[i][1],
                    bbase + SW128((t * 8 + l7) * 128 + kb + sel16));
        }
        #pragma unroll
        for (int mt = 0; mt < 2; ++mt)
            #pragma unroll
            for (int i = 0; i < 7; ++i)
                MMA16816(cacc[mt][i], a[mt], b[i][0], b[i][1]);
    }
}

// chunk-0 k-tile loop with incremental B waits (literal wait_group immediates).
// Pending after prologue commits: {A0, B0..B5, A1}. At step KT we need
// A0 + B0..BKT -> allowed pending = (5-KT) B groups + A1 = 6-KT.
template <int KT>
__device__ __forceinline__ void chunk0_loop(uint32_t abase0, uint32_t bbase0,
                                            int w, int lane, float (&cacc)[2][7][4]) {
    if constexpr (KT < 6) {
        cp_wait_n<6 - KT>();
        __syncthreads();
        gemm_kt_r7(abase0 + KT * A_KT_STRIDE, bbase0 + KT * B_KT_STRIDE,
                   w, lane, cacc);
        chunk0_loop<KT + 1>(abase0, bbase0, w, lane, cacc);
    }
}

// ---------------- Kernel 2: support-resident fused HMMA + max + top6 ----------
__global__ __launch_bounds__(THREADS, 1)
void protonet_hmma_kernel(const float* __restrict__ scale_cls,
                          const float* __restrict__ bias,
                          float* __restrict__ out) {
    extern __shared__ char sm[];
    const uint32_t smb = smem_u32(sm);
    float* pmax4 = reinterpret_cast<float*>(sm + SM_PM);   // [4][224]
    const int tid = threadIdx.x;
    const int w = tid >> 5;
    const int lane = tid & 31;
    const int c = blockIdx.x;     // class fast -> query chunk L2 reuse
    const int m = blockIdx.y;

    const __nv_bfloat16* qbase = g_qbf + (size_t)m * P * D;
    const __nv_bfloat16* sbase = g_sbf + (size_t)c * SROWS * D;

    // query chunk loader: 32 rows x 384 cols bf16, SW128, k-tiled into buf
    auto stage_a = [&](int ch, int buf) {
        const uint32_t abase = smb + SM_A + buf * A_BUF_SIZE;
        #pragma unroll
        for (int idx = tid; idx < A_CH_ROWS * 8 * 6; idx += THREADS) {  // 1536 x 16B
            const int kt  = idx >> 8;              // /(32*8)
            const int rem = idx & 255;
            const int row = rem >> 3;
            const int cb  = (rem & 7) << 4;
            const void* src = qbase + (size_t)(ch * A_CH_ROWS + row) * D + kt * 64 + (cb >> 1);
            cp_async16(abase + kt * A_KT_STRIDE + SW128(row * 128 + cb), src);
        }
        cp_commit();
    };

    // prologue: A0 (1 group), B as 6 per-k-tile groups, A1 (1 group)
    stage_a(0, 0);
    #pragma unroll
    for (int kt = 0; kt < 6; ++kt) {
        for (int idx = tid; idx < BROWS * 8; idx += THREADS) {   // 1792 x 16B
            const int row = idx >> 3;
            const int cb  = (idx & 7) << 4;
            const void* src = sbase + (size_t)row * D + kt * 64 + (cb >> 1);
            cp_async16(smb + SM_B + kt * B_KT_STRIDE + SW128(row * 128 + cb), src);
        }
        cp_commit();
    }
    stage_a(1, 1);

    // fold + write per-warp partials for a finished chunk (R7 form)
    auto finish_chunk = [&](int ch, float (&cc)[2][7][4]) {
        float rmax[2][2];
        rmax[0][0] = rmax[0][1] = rmax[1][0] = rmax[1][1] = NEG_BIG;
        #pragma unroll
        for (int i = 0; i < 7; ++i) {
            const int col0 = (w + 4 * i) * 8 + ((lane & 3) << 1);
            if (col0 < P) {   // support col pair valid (196 is even)
                #pragma unroll
                for (int mt = 0; mt < 2; ++mt) {
                    rmax[mt][0] = fmaxf(rmax[mt][0], fmaxf(cc[mt][i][0], cc[mt][i][1]));
                    rmax[mt][1] = fmaxf(rmax[mt][1], fmaxf(cc[mt][i][2], cc[mt][i][3]));
                }
            }
        }
        #pragma unroll
        for (int mt = 0; mt < 2; ++mt) {
            float v0 = rmax[mt][0], v1 = rmax[mt][1];
            #pragma unroll
            for (int off = 1; off <= 2; off <<= 1) {
                v0 = fmaxf(v0, __shfl_xor_sync(0xffffffffu, v0, off));
                v1 = fmaxf(v1, __shfl_xor_sync(0xffffffffu, v1, off));
            }
            if ((lane & 3) == 0) {
                const int r = ch * A_CH_ROWS + mt * 16 + (lane >> 2);
                pmax4[w * BROWS + r]     = v0;
                pmax4[w * BROWS + r + 8] = v1;
            }
        }
    };

    auto reset_acc = [](float (&cc)[2][7][4]) {
        #pragma unroll
        for (int i = 0; i < 2; ++i)
            #pragma unroll
            for (int j = 0; j < 7; ++j)
                #pragma unroll
                for (int k = 0; k < 4; ++k) cc[i][j][k] = 0.0f;
    };

    float cacc[2][7][4];

    // ---- chunk 0: B streams in under compute via incremental waits ----
    reset_acc(cacc);
    chunk0_loop<0>(smb + SM_A, smb + SM_B, w, lane, cacc);
    finish_chunk(0, cacc);

    // ---- chunks 1..6: double-buffered, barrier-free inner loops (B resident) ----
    for (int ch = 1; ch < NCHUNK; ++ch) {
        __syncthreads();               // compute ch-1 done -> buf (ch+1)&1 free
        if (ch + 1 < NCHUNK) { stage_a(ch + 1, (ch + 1) & 1); cp_wait_n<1>(); }
        else                 { cp_wait_n<0>(); }
        __syncthreads();

        const uint32_t abase_ = smb + SM_A + (ch & 1) * A_BUF_SIZE;
        reset_acc(cacc);
        for (int kt = 0; kt < 6; ++kt)
            gemm_kt_r7(abase_ + kt * A_KT_STRIDE, smb + SM_B + kt * B_KT_STRIDE,
                       w, lane, cacc);
        finish_chunk(ch, cacc);
    }
    __syncthreads();

    // combine 4 warp-partials per query row, apply invq
    const float* invq = g_invq + (size_t)m * P;
    for (int r = tid; r < P; r += THREADS) {
        float v = fmaxf(fmaxf(pmax4[r], pmax4[BROWS + r]),
                        fmaxf(pmax4[2 * BROWS + r], pmax4[3 * BROWS + r]));
        pmax4[r] = v * invq[r];
    }
    __syncthreads();

    // warp 0: exact top-6 over pmax4[0..195]
    if (w == 0) {
        float v[7];
        #pragma unroll
        for (int k = 0; k < 7; ++k) {
            const int p = lane + 32 * k;
            v[k] = (p < P) ? pmax4[p] : NEG_BIG;
        }
        float total = 0.0f;
        for (int it = 0; it < 6; ++it) {
            float bv = NEG_BIG; int bk = 0;
            #pragma unroll
            for (int k = 0; k < 7; ++k)
                if (v[k] > bv) { bv = v[k]; bk = k; }
            int bi = lane + 32 * bk;
            #pragma unroll
            for (int off = 16; off; off >>= 1) {
                float ov = __shfl_xor_sync(0xffffffffu, bv, off);
                int   oi = __shfl_xor_sync(0xffffffffu, bi, off);
                if (ov > bv || (ov == bv && oi < bi)) { bv = ov; bi = oi; }
            }
            total += bv;
            if ((bi & 31) == lane) v[bi >> 5] = NEG_BIG;
        }
        if (lane == 0) out[m * NC + c] = scale_cls[0] * (total + bias[0]);
    }
}

// ---------------------------------------------------------------------------
extern "C" void kernel_launch(void* const* d_in, const int* in_sizes, int n_in,
                              void* d_out, int out_size) {
    const float* support   = (const float*)d_in[0];
    const float* query     = (const float*)d_in[1];
    const float* scale_cls = (const float*)d_in[2];
    const float* bias      = (const float*)d_in[3];
    float* out = (float*)d_out;

    // Stage 1: norms + bf16 conversion
    const int nrows = M_IMG * P + NC * P;
    const int blocks = (nrows * 32 + 255) / 256;
    stage_kernel<<<blocks, 256>>>(support, query);

    // Stage 2: fused HMMA GEMM + reductions (set attribute every call; capture-safe)
    cudaFuncSetAttribute(protonet_hmma_kernel,
                         cudaFuncAttributeMaxDynamicSharedMemorySize, SM_TOTAL);
    dim3 grid(NC, M_IMG);
    protonet_hmma_kernel<<<grid, THREADS, SM_TOTAL>>>(scale_cls, bias, out);
}